// round 11
// baseline (speedup 1.0000x reference)
#include <cuda_runtime.h>
#include <cuda_bf16.h>
#include <mma.h>
#include <math.h>
#include <stdint.h>

using namespace nvcuda;

#define B_   16
#define T_   8
#define C_   2048
#define H_   16
#define D_   128
#define MAXSEQ 4096
#define M_   (B_*T_)      // 128
#define N3_  (3*C_)       // 6144
#define NS   16
#define CHUNK (MAXSEQ/NS) // 256
#define STG  8            // keys per pipeline stage
#define NSTG (CHUNK/STG)  // 32

// ---------------- scratch ----------------
__device__ __align__(16) float g_qkv[M_ * N3_];
__device__ __align__(16) float g_part[4 * M_ * N3_];
__device__ __align__(16) float g_pacc[B_*H_ * NS * T_ * D_];
__device__               float g_pl[B_*H_ * NS * T_];
__device__ __align__(16) float g_y[M_ * C_];

// ---------------- helpers ----------------
__device__ __forceinline__ void fma2(unsigned long long& d,
                                     unsigned long long a,
                                     unsigned long long b) {
    asm("fma.rn.f32x2 %0, %1, %2, %0;" : "+l"(d) : "l"(a), "l"(b));
}
__device__ __forceinline__ void unpk(unsigned long long d, float& x, float& y) {
    asm("mov.b64 {%0, %1}, %2;" : "=f"(x), "=f"(y) : "l"(d));
}
__device__ __forceinline__ float ex2(float x) {
    float r; asm("ex2.approx.f32 %0, %1;" : "=f"(r) : "f"(x)); return r;
}
__device__ __forceinline__ uint32_t smem_u32(const void* p) {
    uint32_t a;
    asm("{ .reg .u64 t; cvta.to.shared.u64 t, %1; cvt.u32.u64 %0, t; }"
        : "=r"(a) : "l"(p));
    return a;
}
__device__ __forceinline__ uint4 pack_hi(float4 a, float4 b) {
    union { __nv_bfloat162 h[4]; uint4 u; } r;
    r.h[0] = __floats2bfloat162_rn(a.x, a.y);
    r.h[1] = __floats2bfloat162_rn(a.z, a.w);
    r.h[2] = __floats2bfloat162_rn(b.x, b.y);
    r.h[3] = __floats2bfloat162_rn(b.z, b.w);
    return r.u;
}
__device__ __forceinline__ uint4 pack_lo(float4 a, float4 b, uint4 hu) {
    union { __nv_bfloat162 h[4]; uint4 u; } hh; hh.u = hu;
    union { __nv_bfloat162 h[4]; uint4 u; } r;
    float2 f0 = __bfloat1622float2(hh.h[0]);
    float2 f1 = __bfloat1622float2(hh.h[1]);
    float2 f2 = __bfloat1622float2(hh.h[2]);
    float2 f3 = __bfloat1622float2(hh.h[3]);
    r.h[0] = __floats2bfloat162_rn(a.x - f0.x, a.y - f0.y);
    r.h[1] = __floats2bfloat162_rn(a.z - f1.x, a.w - f1.y);
    r.h[2] = __floats2bfloat162_rn(b.x - f2.x, b.y - f2.y);
    r.h[3] = __floats2bfloat162_rn(b.z - f3.x, b.w - f3.y);
    return r.u;
}

// ---------------- fused-convert, pipelined WMMA split-K GEMM ----------------
#define ASTRIDE 48
#define BSTRIDE 80
__global__ __launch_bounds__(256) void gemm_f32(
    const float* __restrict__ A, const float* __restrict__ Bm,
    float* __restrict__ Part, int K, int N, int kz)
{
    __shared__ __nv_bfloat16 Ash[128][ASTRIDE], Asl[128][ASTRIDE];
    __shared__ __nv_bfloat16 Bsh[32][BSTRIDE],  Bsl[32][BSTRIDE];

    const int tid = threadIdx.x;
    const int n0  = blockIdx.x * 64;
    const int z   = blockIdx.z;
    const int w   = tid >> 5;
    const int wm  = (w & 3) * 32;
    const int wn  = (w >> 2) * 32;

    wmma::fragment<wmma::accumulator, 16, 16, 16, float> acc[2][2];
#pragma unroll
    for (int i = 0; i < 2; i++)
#pragma unroll
        for (int j = 0; j < 2; j++) wmma::fill_fragment(acc[i][j], 0.f);

    const int ar = tid >> 1, ac = (tid & 1) * 16;
    const int br = tid >> 3, bc = (tid & 7) * 8;
    const int kbeg = z * kz, kend = kbeg + kz;

    float4 a0, a1, a2, a3, b0, b1;
    {
        const float* pa = A + (size_t)ar * K + kbeg + ac;
        a0 = *(const float4*)(pa);     a1 = *(const float4*)(pa + 4);
        a2 = *(const float4*)(pa + 8); a3 = *(const float4*)(pa + 12);
        const float* pb = Bm + (size_t)(kbeg + br) * N + n0 + bc;
        b0 = *(const float4*)(pb);     b1 = *(const float4*)(pb + 4);
    }

    for (int k0 = kbeg; k0 < kend; k0 += 32) {
        {
            uint4 h;
            h = pack_hi(a0, a1);
            *(uint4*)(&Ash[ar][ac])     = h; *(uint4*)(&Asl[ar][ac])     = pack_lo(a0, a1, h);
            h = pack_hi(a2, a3);
            *(uint4*)(&Ash[ar][ac + 8]) = h; *(uint4*)(&Asl[ar][ac + 8]) = pack_lo(a2, a3, h);
            h = pack_hi(b0, b1);
            *(uint4*)(&Bsh[br][bc])     = h; *(uint4*)(&Bsl[br][bc])     = pack_lo(b0, b1, h);
        }
        __syncthreads();
        if (k0 + 32 < kend) {
            const float* pa = A + (size_t)ar * K + (k0 + 32) + ac;
            a0 = *(const float4*)(pa);     a1 = *(const float4*)(pa + 4);
            a2 = *(const float4*)(pa + 8); a3 = *(const float4*)(pa + 12);
            const float* pb = Bm + (size_t)(k0 + 32 + br) * N + n0 + bc;
            b0 = *(const float4*)(pb);     b1 = *(const float4*)(pb + 4);
        }
#pragma unroll
        for (int ks = 0; ks < 2; ks++) {
            wmma::fragment<wmma::matrix_a, 16, 16, 16, __nv_bfloat16, wmma::row_major> ah[2], al[2];
            wmma::fragment<wmma::matrix_b, 16, 16, 16, __nv_bfloat16, wmma::row_major> bh[2], bl[2];
#pragma unroll
            for (int i = 0; i < 2; i++) {
                wmma::load_matrix_sync(ah[i], &Ash[wm + i * 16][ks * 16], ASTRIDE);
                wmma::load_matrix_sync(al[i], &Asl[wm + i * 16][ks * 16], ASTRIDE);
            }
#pragma unroll
            for (int j = 0; j < 2; j++) {
                wmma::load_matrix_sync(bh[j], &Bsh[ks * 16][wn + j * 16], BSTRIDE);
                wmma::load_matrix_sync(bl[j], &Bsl[ks * 16][wn + j * 16], BSTRIDE);
            }
#pragma unroll
            for (int i = 0; i < 2; i++)
#pragma unroll
                for (int j = 0; j < 2; j++) {
                    wmma::mma_sync(acc[i][j], ah[i], bh[j], acc[i][j]);
                    wmma::mma_sync(acc[i][j], ah[i], bl[j], acc[i][j]);
                    wmma::mma_sync(acc[i][j], al[i], bh[j], acc[i][j]);
                }
        }
        __syncthreads();
    }

    float* dst = Part + (size_t)z * M_ * N;
#pragma unroll
    for (int i = 0; i < 2; i++)
#pragma unroll
        for (int j = 0; j < 2; j++)
            wmma::store_matrix_sync(dst + (size_t)(wm + i * 16) * N + n0 + wn + j * 16,
                                    acc[i][j], N, wmma::mem_row_major);
}

// ---------------- combine split-K partials + bias ----------------
__global__ __launch_bounds__(256) void combine_sk(
    const float* __restrict__ Part, const float* __restrict__ bias,
    float* __restrict__ Out, int MN, int N, int S)
{
    int i4 = blockIdx.x * 256 + threadIdx.x;
    int f = i4 * 4;
    if (f >= MN) return;
    float4 s = *(const float4*)(Part + f);
    for (int z = 1; z < S; z++) {
        float4 p = *(const float4*)(Part + (size_t)z * MN + f);
        s.x += p.x; s.y += p.y; s.z += p.z; s.w += p.w;
    }
    float4 bb = *(const float4*)(bias + (f % N));
    s.x += bb.x; s.y += bb.y; s.z += bb.z; s.w += bb.w;
    *(float4*)(Out + f) = s;
}

// ---------------- attention partials: cp.async pipelined flash-decoding ----
// lane = (key8 0-7, dquarter 0-3); 8-key stages, double-buffered cp.async.
// dyn smem: Qs[8][128] | Ks[4][2][8][128] | Ps[4][8][8] float2  ~= 38KB
#define ATTN_SMEM (4096 + 4*2*STG*128*4 + 4*8*8*8)

__global__ __launch_bounds__(128) void attn_partial(
    const float* __restrict__ kc, const float* __restrict__ vc,
    const int* __restrict__ p_start, const int* __restrict__ p_causal)
{
    extern __shared__ __align__(16) char smraw[];
    float*  Qs = (float*)smraw;                         // 1024 floats
    float*  Ks = Qs + T_ * D_;                          // 4*2*STG*128
    float2* Ps = (float2*)(Ks + 4 * 2 * STG * 128);     // [4][8][8]

    const int tid  = threadIdx.x;
    const int w    = tid >> 5;
    const int lane = tid & 31;
    const int bh    = blockIdx.x >> 2;
    const int split = ((blockIdx.x & 3) << 2) | w;
    const int b = bh >> 4, h = bh & 15;

    const int start_pos = *p_start;
    const int causal    = *p_causal;
    const int S = start_pos + T_;
    const float QSCALE = 0.08838834764831845f * 1.4426950408889634f;

    for (int i = tid; i < T_ * 32; i += 128) {
        int t = i >> 5, dq = (i & 31) * 4;
        float4 v = *(const float4*)(g_qkv + (size_t)(b * T_ + t) * N3_ + h * D_ + dq);
        v.x *= QSCALE; v.y *= QSCALE; v.z *= QSCALE; v.w *= QSCALE;
        *(float4*)(&Qs[t * D_ + dq]) = v;
    }
    __syncthreads();

    unsigned long long acc[T_][2];
    float lacc[T_];
#pragma unroll
    for (int t = 0; t < T_; t++) { acc[t][0] = 0ull; acc[t][1] = 0ull; lacc[t] = 0.f; }

    const int s0 = split * CHUNK;
    const float* kbase = kc + (size_t)bh * MAXSEQ * D_;
    const float* vbase = vc + (size_t)bh * MAXSEQ * D_;
    const float* kqkv  = g_qkv + (size_t)(b * T_) * N3_ + C_ + h * D_;
    const float* vqkv  = g_qkv + (size_t)(b * T_) * N3_ + 2 * C_ + h * D_;
    const int key8 = lane & 7;
    const int dh   = lane >> 3;          // 0..3 d-quarter

    float* kwarp = Ks + (size_t)w * 2 * STG * 128;

    auto issueK = [&](int st, int buf) {
        const int sb = s0 + st * STG;
        float* kbuf = kwarp + buf * STG * 128;
#pragma unroll
        for (int r = 0; r < STG; r++) {
            int s = sb + r; if (s >= S) s = S - 1;
            const float* krow = (s < start_pos)
                ? (kbase + (size_t)s * D_)
                : (kqkv + (size_t)(s - start_pos) * N3_);
            uint32_t dst = smem_u32(kbuf + r * 128 + ((lane ^ r) * 4));
            asm volatile("cp.async.cg.shared.global [%0], [%1], 16;"
                         :: "r"(dst), "l"(krow + lane * 4) : "memory");
        }
        asm volatile("cp.async.commit_group;" ::: "memory");
    };

    issueK(0, 0);
    issueK(1, 1);

    for (int st = 0; st < NSTG; st++) {
        const int sb  = s0 + st * STG;
        const int buf = st & 1;

        if (st == NSTG - 1)
            asm volatile("cp.async.wait_group 0;" ::: "memory");
        else
            asm volatile("cp.async.wait_group 1;" ::: "memory");
        __syncwarp();

        // prefetch V rows for this stage (in flight over score phase)
        ulonglong2 vv[STG];
#pragma unroll
        for (int u = 0; u < STG; u++) {
            int s = sb + u; if (s >= S) s = S - 1;
            const float* vrow = (s < start_pos)
                ? (vbase + (size_t)s * D_)
                : (vqkv + (size_t)(s - start_pos) * N3_);
            vv[u] = *(const ulonglong2*)(vrow + lane * 4);
        }

        // scores: lane = (key8, dh quarter of D)
        unsigned long long sc2[T_];
#pragma unroll
        for (int t = 0; t < T_; t++) sc2[t] = 0ull;
        const float* kp = kwarp + buf * STG * 128 + key8 * 128;
#pragma unroll
        for (int dq = 0; dq < 8; dq++) {
            int v = dh * 8 + dq;                 // float4-group 0..31
            int c = v ^ key8;
            ulonglong2 k2 = *(const ulonglong2*)(kp + c * 4);
#pragma unroll
            for (int t = 0; t < T_; t++) {
                ulonglong2 q2 = *(const ulonglong2*)(&Qs[t * D_ + v * 4]);
                fma2(sc2[t], q2.x, k2.x);
                fma2(sc2[t], q2.y, k2.y);
            }
        }
        const int s_key = sb + key8;
        const bool valid = (s_key < S);
#pragma unroll
        for (int t = 0; t < T_; t++) {
            float a, c; unpk(sc2[t], a, c);
            float v = a + c;
            v += __shfl_xor_sync(0xffffffffu, v, 8);
            v += __shfl_xor_sync(0xffffffffu, v, 16);
            float p = (valid && !(causal && s_key > t)) ? ex2(v) : 0.f;
            if (dh == 0) {
                Ps[(w * T_ + t) * 8 + key8] = make_float2(p, p);
                lacc[t] += p;
            }
        }
        __syncwarp();

        // P @ V: lane owns 4 dims
#pragma unroll
        for (int u = 0; u < STG; u++) {
#pragma unroll
            for (int t = 0; t < T_; t++) {
                unsigned long long p2 =
                    *(const unsigned long long*)(&Ps[(w * T_ + t) * 8 + u]);
                fma2(acc[t][0], p2, vv[u].x);
                fma2(acc[t][1], p2, vv[u].y);
            }
        }
        __syncwarp();

        if (st + 2 < NSTG) issueK(st + 2, buf);
    }

    const int pbase = (bh * NS + split) * T_;
#pragma unroll
    for (int t = 0; t < T_; t++) {
        float4 o;
        unpk(acc[t][0], o.x, o.y);
        unpk(acc[t][1], o.z, o.w);
        *(float4*)(g_pacc + (size_t)(pbase + t) * D_ + lane * 4) = o;
        float l = lacc[t];
#pragma unroll
        for (int o2 = 16; o2; o2 >>= 1) l += __shfl_xor_sync(0xffffffffu, l, o2);
        if (lane == 0) g_pl[pbase + t] = l;
    }
}

// ---------------- combine attention splits ----------------
__global__ __launch_bounds__(128) void attn_combine()
{
    const int bht = blockIdx.x;
    const int bh = bht >> 3, t = bht & 7;
    const int d  = threadIdx.x;
    const int b = bh >> 4, h = bh & 15;
    float L = 0.f, y = 0.f;
#pragma unroll
    for (int si = 0; si < NS; si++) {
        L += g_pl[(bh * NS + si) * T_ + t];
        y += g_pacc[(size_t)((bh * NS + si) * T_ + t) * D_ + d];
    }
    g_y[(size_t)(b * T_ + t) * C_ + h * D_ + d] = (L > 0.f) ? (y / L) : 0.f;
}

// ---------------- launch ----------------
extern "C" void kernel_launch(void* const* d_in, const int* in_sizes, int n_in,
                              void* d_out, int out_size)
{
    const float* x      = (const float*)d_in[0];
    const float* kc     = (const float*)d_in[1];
    const float* vc     = (const float*)d_in[2];
    const float* w_attn = (const float*)d_in[3];
    const float* b_attn = (const float*)d_in[4];
    const float* w_proj = (const float*)d_in[5];
    const float* b_proj = (const float*)d_in[6];
    const int*   sp     = (const int*)d_in[7];
    const int*   ic     = (const int*)d_in[8];
    float* out = (float*)d_out;

    static bool attr = false;
    if (!attr) {
        cudaFuncSetAttribute(attn_partial,
                             cudaFuncAttributeMaxDynamicSharedMemorySize, ATTN_SMEM);
        attr = true;
    }

    float *qkv, *y, *part;
    cudaGetSymbolAddress((void**)&qkv,  g_qkv);
    cudaGetSymbolAddress((void**)&y,    g_y);
    cudaGetSymbolAddress((void**)&part, g_part);

    // QKV projection (fused convert, split-K=4)
    gemm_f32<<<dim3(N3_ / 64, 1, 4), 256>>>(x, w_attn, part, C_, N3_, C_ / 4);
    combine_sk<<<(M_ * N3_ / 4) / 256, 256>>>(part, b_attn, qkv, M_ * N3_, N3_, 4);

    // attention
    attn_partial<<<B_ * H_ * 4, 128, ATTN_SMEM>>>(kc, vc, sp, ic);
    attn_combine<<<B_ * H_ * T_, 128>>>();

    // output projection (fused convert, split-K=8)
    gemm_f32<<<dim3(C_ / 64, 1, 8), 256>>>(y, w_proj, part, C_, C_, C_ / 8);
    combine_sk<<<(M_ * C_ / 4) / 256, 256>>>(part, b_proj, out, M_ * C_, C_, 8);
}

// round 12
// speedup vs baseline: 1.0608x; 1.0608x over previous
#include <cuda_runtime.h>
#include <cuda_bf16.h>
#include <mma.h>
#include <math.h>
#include <stdint.h>

using namespace nvcuda;

#define B_   16
#define T_   8
#define C_   2048
#define H_   16
#define D_   128
#define MAXSEQ 4096
#define M_   (B_*T_)      // 128
#define N3_  (3*C_)       // 6144
#define NS   32           // kv splits (tail-quantization fix)
#define CHUNK (MAXSEQ/NS) // 128
#define STG  16           // keys per pipeline stage (R10 proven)
#define NSTG (CHUNK/STG)  // 8

// ---------------- scratch ----------------
__device__ __align__(16) float g_qkv[M_ * N3_];
__device__ __align__(16) float g_part[4 * M_ * N3_];
__device__ __align__(16) float g_pacc[B_*H_ * NS * T_ * D_];
__device__               float g_pl[B_*H_ * NS * T_];
__device__ __align__(16) float g_y[M_ * C_];

// ---------------- helpers ----------------
__device__ __forceinline__ void fma2(unsigned long long& d,
                                     unsigned long long a,
                                     unsigned long long b) {
    asm("fma.rn.f32x2 %0, %1, %2, %0;" : "+l"(d) : "l"(a), "l"(b));
}
__device__ __forceinline__ void unpk(unsigned long long d, float& x, float& y) {
    asm("mov.b64 {%0, %1}, %2;" : "=f"(x), "=f"(y) : "l"(d));
}
__device__ __forceinline__ float ex2(float x) {
    float r; asm("ex2.approx.f32 %0, %1;" : "=f"(r) : "f"(x)); return r;
}
__device__ __forceinline__ uint32_t smem_u32(const void* p) {
    uint32_t a;
    asm("{ .reg .u64 t; cvta.to.shared.u64 t, %1; cvt.u32.u64 %0, t; }"
        : "=r"(a) : "l"(p));
    return a;
}
__device__ __forceinline__ uint4 pack_hi(float4 a, float4 b) {
    union { __nv_bfloat162 h[4]; uint4 u; } r;
    r.h[0] = __floats2bfloat162_rn(a.x, a.y);
    r.h[1] = __floats2bfloat162_rn(a.z, a.w);
    r.h[2] = __floats2bfloat162_rn(b.x, b.y);
    r.h[3] = __floats2bfloat162_rn(b.z, b.w);
    return r.u;
}
__device__ __forceinline__ uint4 pack_lo(float4 a, float4 b, uint4 hu) {
    union { __nv_bfloat162 h[4]; uint4 u; } hh; hh.u = hu;
    union { __nv_bfloat162 h[4]; uint4 u; } r;
    float2 f0 = __bfloat1622float2(hh.h[0]);
    float2 f1 = __bfloat1622float2(hh.h[1]);
    float2 f2 = __bfloat1622float2(hh.h[2]);
    float2 f3 = __bfloat1622float2(hh.h[3]);
    r.h[0] = __floats2bfloat162_rn(a.x - f0.x, a.y - f0.y);
    r.h[1] = __floats2bfloat162_rn(a.z - f1.x, a.w - f1.y);
    r.h[2] = __floats2bfloat162_rn(b.x - f2.x, b.y - f2.y);
    r.h[3] = __floats2bfloat162_rn(b.z - f3.x, b.w - f3.y);
    return r.u;
}

// ---------------- fused-convert, pipelined WMMA split-K GEMM ----------------
#define ASTRIDE 48
#define BSTRIDE 80
__global__ __launch_bounds__(256) void gemm_f32(
    const float* __restrict__ A, const float* __restrict__ Bm,
    float* __restrict__ Part, int K, int N, int kz)
{
    __shared__ __nv_bfloat16 Ash[128][ASTRIDE], Asl[128][ASTRIDE];
    __shared__ __nv_bfloat16 Bsh[32][BSTRIDE],  Bsl[32][BSTRIDE];

    const int tid = threadIdx.x;
    const int n0  = blockIdx.x * 64;
    const int z   = blockIdx.z;
    const int w   = tid >> 5;
    const int wm  = (w & 3) * 32;
    const int wn  = (w >> 2) * 32;

    wmma::fragment<wmma::accumulator, 16, 16, 16, float> acc[2][2];
#pragma unroll
    for (int i = 0; i < 2; i++)
#pragma unroll
        for (int j = 0; j < 2; j++) wmma::fill_fragment(acc[i][j], 0.f);

    const int ar = tid >> 1, ac = (tid & 1) * 16;
    const int br = tid >> 3, bc = (tid & 7) * 8;
    const int kbeg = z * kz, kend = kbeg + kz;

    float4 a0, a1, a2, a3, b0, b1;
    {
        const float* pa = A + (size_t)ar * K + kbeg + ac;
        a0 = *(const float4*)(pa);     a1 = *(const float4*)(pa + 4);
        a2 = *(const float4*)(pa + 8); a3 = *(const float4*)(pa + 12);
        const float* pb = Bm + (size_t)(kbeg + br) * N + n0 + bc;
        b0 = *(const float4*)(pb);     b1 = *(const float4*)(pb + 4);
    }

    for (int k0 = kbeg; k0 < kend; k0 += 32) {
        {
            uint4 h;
            h = pack_hi(a0, a1);
            *(uint4*)(&Ash[ar][ac])     = h; *(uint4*)(&Asl[ar][ac])     = pack_lo(a0, a1, h);
            h = pack_hi(a2, a3);
            *(uint4*)(&Ash[ar][ac + 8]) = h; *(uint4*)(&Asl[ar][ac + 8]) = pack_lo(a2, a3, h);
            h = pack_hi(b0, b1);
            *(uint4*)(&Bsh[br][bc])     = h; *(uint4*)(&Bsl[br][bc])     = pack_lo(b0, b1, h);
        }
        __syncthreads();
        if (k0 + 32 < kend) {
            const float* pa = A + (size_t)ar * K + (k0 + 32) + ac;
            a0 = *(const float4*)(pa);     a1 = *(const float4*)(pa + 4);
            a2 = *(const float4*)(pa + 8); a3 = *(const float4*)(pa + 12);
            const float* pb = Bm + (size_t)(k0 + 32 + br) * N + n0 + bc;
            b0 = *(const float4*)(pb);     b1 = *(const float4*)(pb + 4);
        }
#pragma unroll
        for (int ks = 0; ks < 2; ks++) {
            wmma::fragment<wmma::matrix_a, 16, 16, 16, __nv_bfloat16, wmma::row_major> ah[2], al[2];
            wmma::fragment<wmma::matrix_b, 16, 16, 16, __nv_bfloat16, wmma::row_major> bh[2], bl[2];
#pragma unroll
            for (int i = 0; i < 2; i++) {
                wmma::load_matrix_sync(ah[i], &Ash[wm + i * 16][ks * 16], ASTRIDE);
                wmma::load_matrix_sync(al[i], &Asl[wm + i * 16][ks * 16], ASTRIDE);
            }
#pragma unroll
            for (int j = 0; j < 2; j++) {
                wmma::load_matrix_sync(bh[j], &Bsh[ks * 16][wn + j * 16], BSTRIDE);
                wmma::load_matrix_sync(bl[j], &Bsl[ks * 16][wn + j * 16], BSTRIDE);
            }
#pragma unroll
            for (int i = 0; i < 2; i++)
#pragma unroll
                for (int j = 0; j < 2; j++) {
                    wmma::mma_sync(acc[i][j], ah[i], bh[j], acc[i][j]);
                    wmma::mma_sync(acc[i][j], ah[i], bl[j], acc[i][j]);
                    wmma::mma_sync(acc[i][j], al[i], bh[j], acc[i][j]);
                }
        }
        __syncthreads();
    }

    float* dst = Part + (size_t)z * M_ * N;
#pragma unroll
    for (int i = 0; i < 2; i++)
#pragma unroll
        for (int j = 0; j < 2; j++)
            wmma::store_matrix_sync(dst + (size_t)(wm + i * 16) * N + n0 + wn + j * 16,
                                    acc[i][j], N, wmma::mem_row_major);
}

// ---------------- combine split-K partials + bias ----------------
__global__ __launch_bounds__(256) void combine_sk(
    const float* __restrict__ Part, const float* __restrict__ bias,
    float* __restrict__ Out, int MN, int N, int S)
{
    int i4 = blockIdx.x * 256 + threadIdx.x;
    int f = i4 * 4;
    if (f >= MN) return;
    float4 s = *(const float4*)(Part + f);
    for (int z = 1; z < S; z++) {
        float4 p = *(const float4*)(Part + (size_t)z * MN + f);
        s.x += p.x; s.y += p.y; s.z += p.z; s.w += p.w;
    }
    float4 bb = *(const float4*)(bias + (f % N));
    s.x += bb.x; s.y += bb.y; s.z += bb.z; s.w += bb.w;
    *(float4*)(Out + f) = s;
}

// ---------------- attention partials: cp.async pipelined flash-decoding ----
// R10-proven 16-key stages; NS=32 for wave balance.
// dyn smem: Qs[8][128] | Ks[4][2][16][128] | Ps[4][8][16] float2  = 72KB
#define ATTN_SMEM (4096 + 4*2*STG*128*4 + 4*8*16*8)

__global__ __launch_bounds__(128) void attn_partial(
    const float* __restrict__ kc, const float* __restrict__ vc,
    const int* __restrict__ p_start, const int* __restrict__ p_causal)
{
    extern __shared__ __align__(16) char smraw[];
    float*  Qs = (float*)smraw;                       // 1024 floats
    float*  Ks = Qs + T_ * D_;                        // 4*2*STG*128 floats
    float2* Ps = (float2*)(Ks + 4 * 2 * STG * 128);   // [4][8][16]

    const int tid  = threadIdx.x;
    const int w    = tid >> 5;
    const int lane = tid & 31;
    const int bh    = blockIdx.x >> 3;                 // NS/4 = 8 groups
    const int split = ((blockIdx.x & 7) << 2) | w;
    const int b = bh >> 4, h = bh & 15;

    const int start_pos = *p_start;
    const int causal    = *p_causal;
    const int S = start_pos + T_;
    const float QSCALE = 0.08838834764831845f * 1.4426950408889634f;

    for (int i = tid; i < T_ * 32; i += 128) {
        int t = i >> 5, dq = (i & 31) * 4;
        float4 v = *(const float4*)(g_qkv + (size_t)(b * T_ + t) * N3_ + h * D_ + dq);
        v.x *= QSCALE; v.y *= QSCALE; v.z *= QSCALE; v.w *= QSCALE;
        *(float4*)(&Qs[t * D_ + dq]) = v;
    }
    __syncthreads();

    unsigned long long acc[T_][2];
    float lacc[T_];
#pragma unroll
    for (int t = 0; t < T_; t++) { acc[t][0] = 0ull; acc[t][1] = 0ull; lacc[t] = 0.f; }

    const int s0 = split * CHUNK;
    const float* kbase = kc + (size_t)bh * MAXSEQ * D_;
    const float* vbase = vc + (size_t)bh * MAXSEQ * D_;
    const float* kqkv  = g_qkv + (size_t)(b * T_) * N3_ + C_ + h * D_;
    const float* vqkv  = g_qkv + (size_t)(b * T_) * N3_ + 2 * C_ + h * D_;
    const int key16 = lane & 15;
    const int dh    = lane >> 4;
    const int kx    = key16 & 7;

    float* kwarp = Ks + (size_t)w * 2 * STG * 128;

    auto issueK = [&](int st, int buf) {
        const int sb = s0 + st * STG;
        float* kbuf = kwarp + buf * STG * 128;
#pragma unroll
        for (int r = 0; r < STG; r++) {
            int s = sb + r; if (s >= S) s = S - 1;
            const float* krow = (s < start_pos)
                ? (kbase + (size_t)s * D_)
                : (kqkv + (size_t)(s - start_pos) * N3_);
            uint32_t dst = smem_u32(kbuf + r * 128 + ((lane ^ (r & 7)) * 4));
            asm volatile("cp.async.cg.shared.global [%0], [%1], 16;"
                         :: "r"(dst), "l"(krow + lane * 4) : "memory");
        }
        asm volatile("cp.async.commit_group;" ::: "memory");
    };

    issueK(0, 0);
    issueK(1, 1);

    for (int st = 0; st < NSTG; st++) {
        const int sb  = s0 + st * STG;
        const int buf = st & 1;

        if (st == NSTG - 1)
            asm volatile("cp.async.wait_group 0;" ::: "memory");
        else
            asm volatile("cp.async.wait_group 1;" ::: "memory");
        __syncwarp();

        // prefetch V rows for this stage (16 LDG.128 in flight over score phase)
        ulonglong2 vv[STG];
#pragma unroll
        for (int u = 0; u < STG; u++) {
            int s = sb + u; if (s >= S) s = S - 1;
            const float* vrow = (s < start_pos)
                ? (vbase + (size_t)s * D_)
                : (vqkv + (size_t)(s - start_pos) * N3_);
            vv[u] = *(const ulonglong2*)(vrow + lane * 4);
        }

        // scores: lane = (key16, dh half)
        unsigned long long sc2[T_];
#pragma unroll
        for (int t = 0; t < T_; t++) sc2[t] = 0ull;
        const float* kp = kwarp + buf * STG * 128 + key16 * 128;
#pragma unroll 4
        for (int dq = 0; dq < 16; dq++) {
            int v = dh * 16 + dq;
            int c = v ^ kx;
            ulonglong2 k2 = *(const ulonglong2*)(kp + c * 4);
#pragma unroll
            for (int t = 0; t < T_; t++) {
                ulonglong2 q2 = *(const ulonglong2*)(&Qs[t * D_ + v * 4]);
                fma2(sc2[t], q2.x, k2.x);
                fma2(sc2[t], q2.y, k2.y);
            }
        }
        const int s_key = sb + key16;
        const bool valid = (s_key < S);
#pragma unroll
        for (int t = 0; t < T_; t++) {
            float a, c; unpk(sc2[t], a, c);
            float v = a + c;
            v += __shfl_xor_sync(0xffffffffu, v, 16);
            float p = (valid && !(causal && s_key > t)) ? ex2(v) : 0.f;
            if (dh == 0) {
                Ps[(w * T_ + t) * 16 + key16] = make_float2(p, p);
                lacc[t] += p;
            }
        }
        __syncwarp();

        // P @ V: lane owns 4 dims
#pragma unroll
        for (int u = 0; u < STG; u++) {
#pragma unroll
            for (int t = 0; t < T_; t++) {
                unsigned long long p2 =
                    *(const unsigned long long*)(&Ps[(w * T_ + t) * 16 + u]);
                fma2(acc[t][0], p2, vv[u].x);
                fma2(acc[t][1], p2, vv[u].y);
            }
        }
        __syncwarp();

        if (st + 2 < NSTG) issueK(st + 2, buf);
    }

    const int pbase = (bh * NS + split) * T_;
#pragma unroll
    for (int t = 0; t < T_; t++) {
        float4 o;
        unpk(acc[t][0], o.x, o.y);
        unpk(acc[t][1], o.z, o.w);
        *(float4*)(g_pacc + (size_t)(pbase + t) * D_ + lane * 4) = o;
        float l = lacc[t];
#pragma unroll
        for (int o2 = 16; o2; o2 >>= 1) l += __shfl_xor_sync(0xffffffffu, l, o2);
        if (lane == 0) g_pl[pbase + t] = l;
    }
}

// ---------------- combine attention splits ----------------
__global__ __launch_bounds__(128) void attn_combine()
{
    const int bht = blockIdx.x;
    const int bh = bht >> 3, t = bht & 7;
    const int d  = threadIdx.x;
    const int b = bh >> 4, h = bh & 15;
    float L = 0.f, y = 0.f;
#pragma unroll
    for (int si = 0; si < NS; si++) {
        L += g_pl[(bh * NS + si) * T_ + t];
        y += g_pacc[(size_t)((bh * NS + si) * T_ + t) * D_ + d];
    }
    g_y[(size_t)(b * T_ + t) * C_ + h * D_ + d] = (L > 0.f) ? (y / L) : 0.f;
}

// ---------------- launch ----------------
extern "C" void kernel_launch(void* const* d_in, const int* in_sizes, int n_in,
                              void* d_out, int out_size)
{
    const float* x      = (const float*)d_in[0];
    const float* kc     = (const float*)d_in[1];
    const float* vc     = (const float*)d_in[2];
    const float* w_attn = (const float*)d_in[3];
    const float* b_attn = (const float*)d_in[4];
    const float* w_proj = (const float*)d_in[5];
    const float* b_proj = (const float*)d_in[6];
    const int*   sp     = (const int*)d_in[7];
    const int*   ic     = (const int*)d_in[8];
    float* out = (float*)d_out;

    static bool attr = false;
    if (!attr) {
        cudaFuncSetAttribute(attn_partial,
                             cudaFuncAttributeMaxDynamicSharedMemorySize, ATTN_SMEM);
        attr = true;
    }

    float *qkv, *y, *part;
    cudaGetSymbolAddress((void**)&qkv,  g_qkv);
    cudaGetSymbolAddress((void**)&y,    g_y);
    cudaGetSymbolAddress((void**)&part, g_part);

    // QKV projection (fused convert, split-K=4)
    gemm_f32<<<dim3(N3_ / 64, 1, 4), 256>>>(x, w_attn, part, C_, N3_, C_ / 4);
    combine_sk<<<(M_ * N3_ / 4) / 256, 256>>>(part, b_attn, qkv, M_ * N3_, N3_, 4);

    // attention (NS=32 splits, grid = B*H*NS/4 = 2048 CTAs)
    attn_partial<<<B_ * H_ * (NS / 4), 128, ATTN_SMEM>>>(kc, vc, sp, ic);
    attn_combine<<<B_ * H_ * T_, 128>>>();

    // output projection (fused convert, split-K=8)
    gemm_f32<<<dim3(C_ / 64, 1, 8), 256>>>(y, w_proj, part, C_, C_, C_ / 8);
    combine_sk<<<(M_ * C_ / 4) / 256, 256>>>(part, b_proj, out, M_ * C_, C_, 8);
}

// round 13
// speedup vs baseline: 1.1653x; 1.0985x over previous
#include <cuda_runtime.h>
#include <cuda_bf16.h>
#include <mma.h>
#include <math.h>
#include <stdint.h>

using namespace nvcuda;

#define B_   16
#define T_   8
#define C_   2048
#define H_   16
#define D_   128
#define MAXSEQ 4096
#define M_   (B_*T_)      // 128
#define N3_  (3*C_)       // 6144
#define NS   16
#define CHUNK (MAXSEQ/NS) // 256
#define STG  16           // keys per pipeline stage
#define NSTG (CHUNK/STG)  // 16

// ---------------- scratch ----------------
__device__ __align__(16) float g_qkv[M_ * N3_];
__device__ __align__(16) float g_part[8 * M_ * N3_];
__device__ __align__(16) float g_pacc[B_*H_ * NS * T_ * D_];
__device__               float g_pl[B_*H_ * NS * T_];
__device__ __align__(16) float g_y[M_ * C_];

// ---------------- helpers ----------------
__device__ __forceinline__ void fma2(unsigned long long& d,
                                     unsigned long long a,
                                     unsigned long long b) {
    asm("fma.rn.f32x2 %0, %1, %2, %0;" : "+l"(d) : "l"(a), "l"(b));
}
__device__ __forceinline__ void unpk(unsigned long long d, float& x, float& y) {
    asm("mov.b64 {%0, %1}, %2;" : "=f"(x), "=f"(y) : "l"(d));
}
__device__ __forceinline__ float ex2(float x) {
    float r; asm("ex2.approx.f32 %0, %1;" : "=f"(r) : "f"(x)); return r;
}
__device__ __forceinline__ uint32_t smem_u32(const void* p) {
    uint32_t a;
    asm("{ .reg .u64 t; cvta.to.shared.u64 t, %1; cvt.u32.u64 %0, t; }"
        : "=r"(a) : "l"(p));
    return a;
}
__device__ __forceinline__ uint4 pack_hi(float4 a, float4 b) {
    union { __nv_bfloat162 h[4]; uint4 u; } r;
    r.h[0] = __floats2bfloat162_rn(a.x, a.y);
    r.h[1] = __floats2bfloat162_rn(a.z, a.w);
    r.h[2] = __floats2bfloat162_rn(b.x, b.y);
    r.h[3] = __floats2bfloat162_rn(b.z, b.w);
    return r.u;
}
__device__ __forceinline__ uint4 pack_lo(float4 a, float4 b, uint4 hu) {
    union { __nv_bfloat162 h[4]; uint4 u; } hh; hh.u = hu;
    union { __nv_bfloat162 h[4]; uint4 u; } r;
    float2 f0 = __bfloat1622float2(hh.h[0]);
    float2 f1 = __bfloat1622float2(hh.h[1]);
    float2 f2 = __bfloat1622float2(hh.h[2]);
    float2 f3 = __bfloat1622float2(hh.h[3]);
    r.h[0] = __floats2bfloat162_rn(a.x - f0.x, a.y - f0.y);
    r.h[1] = __floats2bfloat162_rn(a.z - f1.x, a.w - f1.y);
    r.h[2] = __floats2bfloat162_rn(b.x - f2.x, b.y - f2.y);
    r.h[3] = __floats2bfloat162_rn(b.z - f3.x, b.w - f3.y);
    return r.u;
}

// ---------------- fused-convert WMMA split-K GEMM, 128x64 tile ----------------
// 128 threads, 4 warps (2m x 2n), warp tile 64x32, K-chunk 32.
// MMA:LDSM ratio 2.0; smem 29.7KB -> 3-4 CTAs/SM.
#define AST 40
#define BST 72
__global__ __launch_bounds__(128) void gemm_f32(
    const float* __restrict__ A, const float* __restrict__ Bm,
    float* __restrict__ Part, int K, int N, int kz)
{
    __shared__ __nv_bfloat16 Ash[128][AST], Asl[128][AST];
    __shared__ __nv_bfloat16 Bsh[32][BST],  Bsl[32][BST];

    const int tid = threadIdx.x;
    const int n0  = blockIdx.x * 64;
    const int z   = blockIdx.z;
    const int w   = tid >> 5;
    const int wm  = (w & 1) * 64;
    const int wn  = (w >> 1) * 32;

    wmma::fragment<wmma::accumulator, 16, 16, 16, float> acc[4][2];
#pragma unroll
    for (int i = 0; i < 4; i++)
#pragma unroll
        for (int j = 0; j < 2; j++) wmma::fill_fragment(acc[i][j], 0.f);

    const int ar = tid;                       // A row, 32 cols per thread
    const int br = tid >> 2, bc = (tid & 3) * 16;  // B: 32 rows x 64 cols
    const int kbeg = z * kz, kend = kbeg + kz;

    float4 a[8], b[4];
    {
        const float* pa = A + (size_t)ar * K + kbeg;
#pragma unroll
        for (int i = 0; i < 8; i++) a[i] = *(const float4*)(pa + i * 4);
        const float* pb = Bm + (size_t)(kbeg + br) * N + n0 + bc;
#pragma unroll
        for (int i = 0; i < 4; i++) b[i] = *(const float4*)(pb + i * 4);
    }

    for (int k0 = kbeg; k0 < kend; k0 += 32) {
        // convert + store current chunk
#pragma unroll
        for (int i = 0; i < 4; i++) {
            uint4 h = pack_hi(a[2 * i], a[2 * i + 1]);
            *(uint4*)(&Ash[ar][i * 8]) = h;
            *(uint4*)(&Asl[ar][i * 8]) = pack_lo(a[2 * i], a[2 * i + 1], h);
        }
#pragma unroll
        for (int i = 0; i < 2; i++) {
            uint4 h = pack_hi(b[2 * i], b[2 * i + 1]);
            *(uint4*)(&Bsh[br][bc + i * 8]) = h;
            *(uint4*)(&Bsl[br][bc + i * 8]) = pack_lo(b[2 * i], b[2 * i + 1], h);
        }
        __syncthreads();
        // prefetch next chunk (overlaps with MMAs below)
        if (k0 + 32 < kend) {
            const float* pa = A + (size_t)ar * K + (k0 + 32);
#pragma unroll
            for (int i = 0; i < 8; i++) a[i] = *(const float4*)(pa + i * 4);
            const float* pb = Bm + (size_t)(k0 + 32 + br) * N + n0 + bc;
#pragma unroll
            for (int i = 0; i < 4; i++) b[i] = *(const float4*)(pb + i * 4);
        }
#pragma unroll
        for (int ks = 0; ks < 2; ks++) {
            wmma::fragment<wmma::matrix_a, 16, 16, 16, __nv_bfloat16, wmma::row_major> ah[4], al[4];
            wmma::fragment<wmma::matrix_b, 16, 16, 16, __nv_bfloat16, wmma::row_major> bh[2], bl[2];
#pragma unroll
            for (int i = 0; i < 4; i++) {
                wmma::load_matrix_sync(ah[i], &Ash[wm + i * 16][ks * 16], AST);
                wmma::load_matrix_sync(al[i], &Asl[wm + i * 16][ks * 16], AST);
            }
#pragma unroll
            for (int j = 0; j < 2; j++) {
                wmma::load_matrix_sync(bh[j], &Bsh[ks * 16][wn + j * 16], BST);
                wmma::load_matrix_sync(bl[j], &Bsl[ks * 16][wn + j * 16], BST);
            }
#pragma unroll
            for (int i = 0; i < 4; i++)
#pragma unroll
                for (int j = 0; j < 2; j++) {
                    wmma::mma_sync(acc[i][j], ah[i], bh[j], acc[i][j]);
                    wmma::mma_sync(acc[i][j], ah[i], bl[j], acc[i][j]);
                    wmma::mma_sync(acc[i][j], al[i], bh[j], acc[i][j]);
                }
        }
        __syncthreads();
    }

    float* dst = Part + (size_t)z * M_ * N;
#pragma unroll
    for (int i = 0; i < 4; i++)
#pragma unroll
        for (int j = 0; j < 2; j++)
            wmma::store_matrix_sync(dst + (size_t)(wm + i * 16) * N + n0 + wn + j * 16,
                                    acc[i][j], N, wmma::mem_row_major);
}

// ---------------- combine split-K partials + bias ----------------
__global__ __launch_bounds__(256) void combine_sk(
    const float* __restrict__ Part, const float* __restrict__ bias,
    float* __restrict__ Out, int MN, int N, int S)
{
    int i4 = blockIdx.x * 256 + threadIdx.x;
    int f = i4 * 4;
    if (f >= MN) return;
    float4 s = *(const float4*)(Part + f);
    for (int z = 1; z < S; z++) {
        float4 p = *(const float4*)(Part + (size_t)z * MN + f);
        s.x += p.x; s.y += p.y; s.z += p.z; s.w += p.w;
    }
    float4 bb = *(const float4*)(bias + (f % N));
    s.x += bb.x; s.y += bb.y; s.z += bb.z; s.w += bb.w;
    *(float4*)(Out + f) = s;
}

// ---------------- attention partials: cp.async pipelined flash-decoding ----
// (exact R10 configuration: NS=16, STG=16)
// dyn smem: Qs[8][128] | Ks[4][2][16][128] | Ps[4][8][16] float2  = 72KB
#define ATTN_SMEM (4096 + 4*2*STG*128*4 + 4*8*16*8)

__global__ __launch_bounds__(128) void attn_partial(
    const float* __restrict__ kc, const float* __restrict__ vc,
    const int* __restrict__ p_start, const int* __restrict__ p_causal)
{
    extern __shared__ __align__(16) char smraw[];
    float*  Qs = (float*)smraw;                       // 1024 floats
    float*  Ks = Qs + T_ * D_;                        // 4*2*STG*128 floats
    float2* Ps = (float2*)(Ks + 4 * 2 * STG * 128);   // [4][8][16]

    const int tid  = threadIdx.x;
    const int w    = tid >> 5;
    const int lane = tid & 31;
    const int bh    = blockIdx.x >> 2;
    const int split = ((blockIdx.x & 3) << 2) | w;
    const int b = bh >> 4, h = bh & 15;

    const int start_pos = *p_start;
    const int causal    = *p_causal;
    const int S = start_pos + T_;
    const float QSCALE = 0.08838834764831845f * 1.4426950408889634f;

    for (int i = tid; i < T_ * 32; i += 128) {
        int t = i >> 5, dq = (i & 31) * 4;
        float4 v = *(const float4*)(g_qkv + (size_t)(b * T_ + t) * N3_ + h * D_ + dq);
        v.x *= QSCALE; v.y *= QSCALE; v.z *= QSCALE; v.w *= QSCALE;
        *(float4*)(&Qs[t * D_ + dq]) = v;
    }
    __syncthreads();

    unsigned long long acc[T_][2];
    float lacc[T_];
#pragma unroll
    for (int t = 0; t < T_; t++) { acc[t][0] = 0ull; acc[t][1] = 0ull; lacc[t] = 0.f; }

    const int s0 = split * CHUNK;
    const float* kbase = kc + (size_t)bh * MAXSEQ * D_;
    const float* vbase = vc + (size_t)bh * MAXSEQ * D_;
    const float* kqkv  = g_qkv + (size_t)(b * T_) * N3_ + C_ + h * D_;
    const float* vqkv  = g_qkv + (size_t)(b * T_) * N3_ + 2 * C_ + h * D_;
    const int key16 = lane & 15;
    const int dh    = lane >> 4;
    const int kx    = key16 & 7;

    float* kwarp = Ks + (size_t)w * 2 * STG * 128;

    auto issueK = [&](int st, int buf) {
        const int sb = s0 + st * STG;
        float* kbuf = kwarp + buf * STG * 128;
#pragma unroll
        for (int r = 0; r < STG; r++) {
            int s = sb + r; if (s >= S) s = S - 1;
            const float* krow = (s < start_pos)
                ? (kbase + (size_t)s * D_)
                : (kqkv + (size_t)(s - start_pos) * N3_);
            uint32_t dst = smem_u32(kbuf + r * 128 + ((lane ^ (r & 7)) * 4));
            asm volatile("cp.async.cg.shared.global [%0], [%1], 16;"
                         :: "r"(dst), "l"(krow + lane * 4) : "memory");
        }
        asm volatile("cp.async.commit_group;" ::: "memory");
    };

    issueK(0, 0);
    issueK(1, 1);

    for (int st = 0; st < NSTG; st++) {
        const int sb  = s0 + st * STG;
        const int buf = st & 1;

        if (st == NSTG - 1)
            asm volatile("cp.async.wait_group 0;" ::: "memory");
        else
            asm volatile("cp.async.wait_group 1;" ::: "memory");
        __syncwarp();

        // prefetch V rows for this stage (16 LDG.128 in flight over score phase)
        ulonglong2 vv[STG];
#pragma unroll
        for (int u = 0; u < STG; u++) {
            int s = sb + u; if (s >= S) s = S - 1;
            const float* vrow = (s < start_pos)
                ? (vbase + (size_t)s * D_)
                : (vqkv + (size_t)(s - start_pos) * N3_);
            vv[u] = *(const ulonglong2*)(vrow + lane * 4);
        }

        // scores: lane = (key16, dh half)
        unsigned long long sc2[T_];
#pragma unroll
        for (int t = 0; t < T_; t++) sc2[t] = 0ull;
        const float* kp = kwarp + buf * STG * 128 + key16 * 128;
#pragma unroll 4
        for (int dq = 0; dq < 16; dq++) {
            int v = dh * 16 + dq;
            int c = v ^ kx;
            ulonglong2 k2 = *(const ulonglong2*)(kp + c * 4);
#pragma unroll
            for (int t = 0; t < T_; t++) {
                ulonglong2 q2 = *(const ulonglong2*)(&Qs[t * D_ + v * 4]);
                fma2(sc2[t], q2.x, k2.x);
                fma2(sc2[t], q2.y, k2.y);
            }
        }
        const int s_key = sb + key16;
        const bool valid = (s_key < S);
#pragma unroll
        for (int t = 0; t < T_; t++) {
            float a, c; unpk(sc2[t], a, c);
            float v = a + c;
            v += __shfl_xor_sync(0xffffffffu, v, 16);
            float p = (valid && !(causal && s_key > t)) ? ex2(v) : 0.f;
            if (dh == 0) {
                Ps[(w * T_ + t) * 16 + key16] = make_float2(p, p);
                lacc[t] += p;
            }
        }
        __syncwarp();

        // P @ V: lane owns 4 dims
#pragma unroll
        for (int u = 0; u < STG; u++) {
#pragma unroll
            for (int t = 0; t < T_; t++) {
                unsigned long long p2 =
                    *(const unsigned long long*)(&Ps[(w * T_ + t) * 16 + u]);
                fma2(acc[t][0], p2, vv[u].x);
                fma2(acc[t][1], p2, vv[u].y);
            }
        }
        __syncwarp();

        if (st + 2 < NSTG) issueK(st + 2, buf);
    }

    const int pbase = (bh * NS + split) * T_;
#pragma unroll
    for (int t = 0; t < T_; t++) {
        float4 o;
        unpk(acc[t][0], o.x, o.y);
        unpk(acc[t][1], o.z, o.w);
        *(float4*)(g_pacc + (size_t)(pbase + t) * D_ + lane * 4) = o;
        float l = lacc[t];
#pragma unroll
        for (int o2 = 16; o2; o2 >>= 1) l += __shfl_xor_sync(0xffffffffu, l, o2);
        if (lane == 0) g_pl[pbase + t] = l;
    }
}

// ---------------- combine attention splits ----------------
__global__ __launch_bounds__(128) void attn_combine()
{
    const int bht = blockIdx.x;
    const int bh = bht >> 3, t = bht & 7;
    const int d  = threadIdx.x;
    const int b = bh >> 4, h = bh & 15;
    float L = 0.f, y = 0.f;
#pragma unroll
    for (int si = 0; si < NS; si++) {
        L += g_pl[(bh * NS + si) * T_ + t];
        y += g_pacc[(size_t)((bh * NS + si) * T_ + t) * D_ + d];
    }
    g_y[(size_t)(b * T_ + t) * C_ + h * D_ + d] = (L > 0.f) ? (y / L) : 0.f;
}

// ---------------- launch ----------------
extern "C" void kernel_launch(void* const* d_in, const int* in_sizes, int n_in,
                              void* d_out, int out_size)
{
    const float* x      = (const float*)d_in[0];
    const float* kc     = (const float*)d_in[1];
    const float* vc     = (const float*)d_in[2];
    const float* w_attn = (const float*)d_in[3];
    const float* b_attn = (const float*)d_in[4];
    const float* w_proj = (const float*)d_in[5];
    const float* b_proj = (const float*)d_in[6];
    const int*   sp     = (const int*)d_in[7];
    const int*   ic     = (const int*)d_in[8];
    float* out = (float*)d_out;

    static bool attr = false;
    if (!attr) {
        cudaFuncSetAttribute(attn_partial,
                             cudaFuncAttributeMaxDynamicSharedMemorySize, ATTN_SMEM);
        attr = true;
    }

    float *qkv, *y, *part;
    cudaGetSymbolAddress((void**)&qkv,  g_qkv);
    cudaGetSymbolAddress((void**)&y,    g_y);
    cudaGetSymbolAddress((void**)&part, g_part);

    // QKV projection (fused convert, 128x64 tiles, split-K=8 -> 768 CTAs)
    gemm_f32<<<dim3(N3_ / 64, 1, 8), 128>>>(x, w_attn, part, C_, N3_, C_ / 8);
    combine_sk<<<(M_ * N3_ / 4) / 256, 256>>>(part, b_attn, qkv, M_ * N3_, N3_, 8);

    // attention (R10 config: NS=16, 1024 CTAs)
    attn_partial<<<B_ * H_ * 4, 128, ATTN_SMEM>>>(kc, vc, sp, ic);
    attn_combine<<<B_ * H_ * T_, 128>>>();

    // output projection (split-K=16 -> 512 CTAs)
    gemm_f32<<<dim3(C_ / 64, 1, 16), 128>>>(y, w_proj, part, C_, C_, C_ / 16);
    combine_sk<<<(M_ * C_ / 4) / 256, 256>>>(part, b_proj, out, M_ * C_, C_, 16);
}

// round 15
// speedup vs baseline: 1.1677x; 1.0021x over previous
#include <cuda_runtime.h>
#include <cuda_bf16.h>
#include <mma.h>
#include <math.h>
#include <stdint.h>

using namespace nvcuda;

#define B_   16
#define T_   8
#define C_   2048
#define H_   16
#define D_   128
#define MAXSEQ 4096
#define M_   (B_*T_)      // 128
#define N3_  (3*C_)       // 6144
#define NS   16
#define CHUNK (MAXSEQ/NS) // 256
#define STG  16           // keys per pipeline stage
#define NSTG (CHUNK/STG)  // 16

// ---------------- scratch ----------------
__device__ __align__(16) float g_qkv[M_ * N3_];
__device__ __align__(16) float g_part[4 * M_ * N3_];
__device__ __align__(16) float g_pacc[B_*H_ * NS * T_ * D_];
__device__               float g_pl[B_*H_ * NS * T_];
__device__ __align__(16) float g_y[M_ * C_];

// ---------------- helpers ----------------
__device__ __forceinline__ void fma2(unsigned long long& d,
                                     unsigned long long a,
                                     unsigned long long b) {
    asm("fma.rn.f32x2 %0, %1, %2, %0;" : "+l"(d) : "l"(a), "l"(b));
}
__device__ __forceinline__ void unpk(unsigned long long d, float& x, float& y) {
    asm("mov.b64 {%0, %1}, %2;" : "=f"(x), "=f"(y) : "l"(d));
}
__device__ __forceinline__ float ex2(float x) {
    float r; asm("ex2.approx.f32 %0, %1;" : "=f"(r) : "f"(x)); return r;
}
__device__ __forceinline__ uint32_t smem_u32(const void* p) {
    uint32_t a;
    asm("{ .reg .u64 t; cvta.to.shared.u64 t, %1; cvt.u32.u64 %0, t; }"
        : "=r"(a) : "l"(p));
    return a;
}
__device__ __forceinline__ uint4 pack_hi(float4 a, float4 b) {
    union { __nv_bfloat162 h[4]; uint4 u; } r;
    r.h[0] = __floats2bfloat162_rn(a.x, a.y);
    r.h[1] = __floats2bfloat162_rn(a.z, a.w);
    r.h[2] = __floats2bfloat162_rn(b.x, b.y);
    r.h[3] = __floats2bfloat162_rn(b.z, b.w);
    return r.u;
}
__device__ __forceinline__ uint4 pack_lo(float4 a, float4 b, uint4 hu) {
    union { __nv_bfloat162 h[4]; uint4 u; } hh; hh.u = hu;
    union { __nv_bfloat162 h[4]; uint4 u; } r;
    float2 f0 = __bfloat1622float2(hh.h[0]);
    float2 f1 = __bfloat1622float2(hh.h[1]);
    float2 f2 = __bfloat1622float2(hh.h[2]);
    float2 f3 = __bfloat1622float2(hh.h[3]);
    r.h[0] = __floats2bfloat162_rn(a.x - f0.x, a.y - f0.y);
    r.h[1] = __floats2bfloat162_rn(a.z - f1.x, a.w - f1.y);
    r.h[2] = __floats2bfloat162_rn(b.x - f2.x, b.y - f2.y);
    r.h[3] = __floats2bfloat162_rn(b.z - f3.x, b.w - f3.y);
    return r.u;
}

// ---------------- fused-convert WMMA split-K GEMM, double-buffered ---------
// 128 threads, 4 warps (2m x 2n), block tile 128x64, warp 64x32, K-chunk 32.
// Dynamic smem: 2 buffers x (Ash/Asl 128x40 + Bsh/Bsl 32x72) bf16 = 59.4KB
#define AST 40
#define BST 72
#define GEMM_BUF_ELE (128*AST*2 + 32*BST*2)   // bf16 elems per buffer
#define GEMM_SMEM (2 * GEMM_BUF_ELE * 2)      // bytes

__global__ __launch_bounds__(128) void gemm_f32(
    const float* __restrict__ A, const float* __restrict__ Bm,
    float* __restrict__ Part, int K, int N, int kz)
{
    extern __shared__ __align__(16) __nv_bfloat16 gsm[];

    const int tid = threadIdx.x;
    const int n0  = blockIdx.x * 64;
    const int z   = blockIdx.z;
    const int w   = tid >> 5;
    const int wm  = (w & 1) * 64;
    const int wn  = (w >> 1) * 32;

    wmma::fragment<wmma::accumulator, 16, 16, 16, float> acc[4][2];
#pragma unroll
    for (int i = 0; i < 4; i++)
#pragma unroll
        for (int j = 0; j < 2; j++) wmma::fill_fragment(acc[i][j], 0.f);

    const int ar = tid;
    const int br = tid >> 2, bc = (tid & 3) * 16;
    const int kbeg = z * kz, kend = kbeg + kz;
    const int nch = kz / 32;

    float4 a[8], b[4];
    auto ldg = [&](int k0) {
        const float* pa = A + (size_t)ar * K + k0;
#pragma unroll
        for (int i = 0; i < 8; i++) a[i] = *(const float4*)(pa + i * 4);
        const float* pb = Bm + (size_t)(k0 + br) * N + n0 + bc;
#pragma unroll
        for (int i = 0; i < 4; i++) b[i] = *(const float4*)(pb + i * 4);
    };
    auto sts = [&](int buf) {
        __nv_bfloat16* Ash = gsm + (size_t)buf * GEMM_BUF_ELE;
        __nv_bfloat16* Asl = Ash + 128 * AST;
        __nv_bfloat16* Bsh = Asl + 128 * AST;
        __nv_bfloat16* Bsl = Bsh + 32 * BST;
#pragma unroll
        for (int i = 0; i < 4; i++) {
            uint4 h = pack_hi(a[2 * i], a[2 * i + 1]);
            *(uint4*)(&Ash[ar * AST + i * 8]) = h;
            *(uint4*)(&Asl[ar * AST + i * 8]) = pack_lo(a[2 * i], a[2 * i + 1], h);
        }
#pragma unroll
        for (int i = 0; i < 2; i++) {
            uint4 h = pack_hi(b[2 * i], b[2 * i + 1]);
            *(uint4*)(&Bsh[br * BST + bc + i * 8]) = h;
            *(uint4*)(&Bsl[br * BST + bc + i * 8]) = pack_lo(b[2 * i], b[2 * i + 1], h);
        }
    };

    // prologue
    ldg(kbeg);
    sts(0);
    __syncthreads();

    for (int c = 0; c < nch; c++) {
        const int buf = c & 1;
        if (c + 1 < nch) ldg(kbeg + (c + 1) * 32);   // LDG early, hidden by MMA

        const __nv_bfloat16* Ash = gsm + (size_t)buf * GEMM_BUF_ELE;
        const __nv_bfloat16* Asl = Ash + 128 * AST;
        const __nv_bfloat16* Bsh = Asl + 128 * AST;
        const __nv_bfloat16* Bsl = Bsh + 32 * BST;
#pragma unroll
        for (int ks = 0; ks < 2; ks++) {
            wmma::fragment<wmma::matrix_a, 16, 16, 16, __nv_bfloat16, wmma::row_major> ah[4], al[4];
            wmma::fragment<wmma::matrix_b, 16, 16, 16, __nv_bfloat16, wmma::row_major> bh[2], bl[2];
#pragma unroll
            for (int i = 0; i < 4; i++) {
                wmma::load_matrix_sync(ah[i], &Ash[(wm + i * 16) * AST + ks * 16], AST);
                wmma::load_matrix_sync(al[i], &Asl[(wm + i * 16) * AST + ks * 16], AST);
            }
#pragma unroll
            for (int j = 0; j < 2; j++) {
                wmma::load_matrix_sync(bh[j], &Bsh[(ks * 16) * BST + wn + j * 16], BST);
                wmma::load_matrix_sync(bl[j], &Bsl[(ks * 16) * BST + wn + j * 16], BST);
            }
#pragma unroll
            for (int i = 0; i < 4; i++)
#pragma unroll
                for (int j = 0; j < 2; j++) {
                    wmma::mma_sync(acc[i][j], ah[i], bh[j], acc[i][j]);
                    wmma::mma_sync(acc[i][j], ah[i], bl[j], acc[i][j]);
                    wmma::mma_sync(acc[i][j], al[i], bh[j], acc[i][j]);
                }
        }
        if (c + 1 < nch) {
            sts(buf ^ 1);
            __syncthreads();
        }
    }

    float* dst = Part + (size_t)z * M_ * N;
#pragma unroll
    for (int i = 0; i < 4; i++)
#pragma unroll
        for (int j = 0; j < 2; j++)
            wmma::store_matrix_sync(dst + (size_t)(wm + i * 16) * N + n0 + wn + j * 16,
                                    acc[i][j], N, wmma::mem_row_major);
}

// ---------------- combine split-K partials + bias ----------------
__global__ __launch_bounds__(256) void combine_sk(
    const float* __restrict__ Part, const float* __restrict__ bias,
    float* __restrict__ Out, int MN, int N, int S)
{
    int i4 = blockIdx.x * 256 + threadIdx.x;
    int f = i4 * 4;
    if (f >= MN) return;
    float4 s = *(const float4*)(Part + f);
    for (int z = 1; z < S; z++) {
        float4 p = *(const float4*)(Part + (size_t)z * MN + f);
        s.x += p.x; s.y += p.y; s.z += p.z; s.w += p.w;
    }
    float4 bb = *(const float4*)(bias + (f % N));
    s.x += bb.x; s.y += bb.y; s.z += bb.z; s.w += bb.w;
    *(float4*)(Out + f) = s;
}

// ---------------- attention partials: cp.async pipelined flash-decoding ----
// (frozen R10 configuration: NS=16, STG=16)
#define ATTN_SMEM (4096 + 4*2*STG*128*4 + 4*8*16*8)

__global__ __launch_bounds__(128) void attn_partial(
    const float* __restrict__ kc, const float* __restrict__ vc,
    const int* __restrict__ p_start, const int* __restrict__ p_causal)
{
    extern __shared__ __align__(16) char smraw[];
    float*  Qs = (float*)smraw;
    float*  Ks = Qs + T_ * D_;
    float2* Ps = (float2*)(Ks + 4 * 2 * STG * 128);

    const int tid  = threadIdx.x;
    const int w    = tid >> 5;
    const int lane = tid & 31;
    const int bh    = blockIdx.x >> 2;
    const int split = ((blockIdx.x & 3) << 2) | w;
    const int b = bh >> 4, h = bh & 15;

    const int start_pos = *p_start;
    const int causal    = *p_causal;
    const int S = start_pos + T_;
    const float QSCALE = 0.08838834764831845f * 1.4426950408889634f;

    for (int i = tid; i < T_ * 32; i += 128) {
        int t = i >> 5, dq = (i & 31) * 4;
        float4 v = *(const float4*)(g_qkv + (size_t)(b * T_ + t) * N3_ + h * D_ + dq);
        v.x *= QSCALE; v.y *= QSCALE; v.z *= QSCALE; v.w *= QSCALE;
        *(float4*)(&Qs[t * D_ + dq]) = v;
    }
    __syncthreads();

    unsigned long long acc[T_][2];
    float lacc[T_];
#pragma unroll
    for (int t = 0; t < T_; t++) { acc[t][0] = 0ull; acc[t][1] = 0ull; lacc[t] = 0.f; }

    const int s0 = split * CHUNK;
    const float* kbase = kc + (size_t)bh * MAXSEQ * D_;
    const float* vbase = vc + (size_t)bh * MAXSEQ * D_;
    const float* kqkv  = g_qkv + (size_t)(b * T_) * N3_ + C_ + h * D_;
    const float* vqkv  = g_qkv + (size_t)(b * T_) * N3_ + 2 * C_ + h * D_;
    const int key16 = lane & 15;
    const int dh    = lane >> 4;
    const int kx    = key16 & 7;

    float* kwarp = Ks + (size_t)w * 2 * STG * 128;

    auto issueK = [&](int st, int buf) {
        const int sb = s0 + st * STG;
        float* kbuf = kwarp + buf * STG * 128;
#pragma unroll
        for (int r = 0; r < STG; r++) {
            int s = sb + r; if (s >= S) s = S - 1;
            const float* krow = (s < start_pos)
                ? (kbase + (size_t)s * D_)
                : (kqkv + (size_t)(s - start_pos) * N3_);
            uint32_t dst = smem_u32(kbuf + r * 128 + ((lane ^ (r & 7)) * 4));
            asm volatile("cp.async.cg.shared.global [%0], [%1], 16;"
                         :: "r"(dst), "l"(krow + lane * 4) : "memory");
        }
        asm volatile("cp.async.commit_group;" ::: "memory");
    };

    issueK(0, 0);
    issueK(1, 1);

    for (int st = 0; st < NSTG; st++) {
        const int sb  = s0 + st * STG;
        const int buf = st & 1;

        if (st == NSTG - 1)
            asm volatile("cp.async.wait_group 0;" ::: "memory");
        else
            asm volatile("cp.async.wait_group 1;" ::: "memory");
        __syncwarp();

        ulonglong2 vv[STG];
#pragma unroll
        for (int u = 0; u < STG; u++) {
            int s = sb + u; if (s >= S) s = S - 1;
            const float* vrow = (s < start_pos)
                ? (vbase + (size_t)s * D_)
                : (vqkv + (size_t)(s - start_pos) * N3_);
            vv[u] = *(const ulonglong2*)(vrow + lane * 4);
        }

        unsigned long long sc2[T_];
#pragma unroll
        for (int t = 0; t < T_; t++) sc2[t] = 0ull;
        const float* kp = kwarp + buf * STG * 128 + key16 * 128;
#pragma unroll 4
        for (int dq = 0; dq < 16; dq++) {
            int v = dh * 16 + dq;
            int c = v ^ kx;
            ulonglong2 k2 = *(const ulonglong2*)(kp + c * 4);
#pragma unroll
            for (int t = 0; t < T_; t++) {
                ulonglong2 q2 = *(const ulonglong2*)(&Qs[t * D_ + v * 4]);
                fma2(sc2[t], q2.x, k2.x);
                fma2(sc2[t], q2.y, k2.y);
            }
        }
        const int s_key = sb + key16;
        const bool valid = (s_key < S);
#pragma unroll
        for (int t = 0; t < T_; t++) {
            float a, c; unpk(sc2[t], a, c);
            float v = a + c;
            v += __shfl_xor_sync(0xffffffffu, v, 16);
            float p = (valid && !(causal && s_key > t)) ? ex2(v) : 0.f;
            if (dh == 0) {
                Ps[(w * T_ + t) * 16 + key16] = make_float2(p, p);
                lacc[t] += p;
            }
        }
        __syncwarp();

#pragma unroll
        for (int u = 0; u < STG; u++) {
#pragma unroll
            for (int t = 0; t < T_; t++) {
                unsigned long long p2 =
                    *(const unsigned long long*)(&Ps[(w * T_ + t) * 16 + u]);
                fma2(acc[t][0], p2, vv[u].x);
                fma2(acc[t][1], p2, vv[u].y);
            }
        }
        __syncwarp();

        if (st + 2 < NSTG) issueK(st + 2, buf);
    }

    const int pbase = (bh * NS + split) * T_;
#pragma unroll
    for (int t = 0; t < T_; t++) {
        float4 o;
        unpk(acc[t][0], o.x, o.y);
        unpk(acc[t][1], o.z, o.w);
        *(float4*)(g_pacc + (size_t)(pbase + t) * D_ + lane * 4) = o;
        float l = lacc[t];
#pragma unroll
        for (int o2 = 16; o2; o2 >>= 1) l += __shfl_xor_sync(0xffffffffu, l, o2);
        if (lane == 0) g_pl[pbase + t] = l;
    }
}

// ---------------- combine attention splits ----------------
__global__ __launch_bounds__(128) void attn_combine()
{
    const int bht = blockIdx.x;
    const int bh = bht >> 3, t = bht & 7;
    const int d  = threadIdx.x;
    const int b = bh >> 4, h = bh & 15;
    float L = 0.f, y = 0.f;
#pragma unroll
    for (int si = 0; si < NS; si++) {
        L += g_pl[(bh * NS + si) * T_ + t];
        y += g_pacc[(size_t)((bh * NS + si) * T_ + t) * D_ + d];
    }
    g_y[(size_t)(b * T_ + t) * C_ + h * D_ + d] = (L > 0.f) ? (y / L) : 0.f;
}

// ---------------- launch ----------------
extern "C" void kernel_launch(void* const* d_in, const int* in_sizes, int n_in,
                              void* d_out, int out_size)
{
    const float* x      = (const float*)d_in[0];
    const float* kc     = (const float*)d_in[1];
    const float* vc     = (const float*)d_in[2];
    const float* w_attn = (const float*)d_in[3];
    const float* b_attn = (const float*)d_in[4];
    const float* w_proj = (const float*)d_in[5];
    const float* b_proj = (const float*)d_in[6];
    const int*   sp     = (const int*)d_in[7];
    const int*   ic     = (const int*)d_in[8];
    float* out = (float*)d_out;

    static bool attr = false;
    if (!attr) {
        cudaFuncSetAttribute(attn_partial,
                             cudaFuncAttributeMaxDynamicSharedMemorySize, ATTN_SMEM);
        cudaFuncSetAttribute(gemm_f32,
                             cudaFuncAttributeMaxDynamicSharedMemorySize, GEMM_SMEM);
        attr = true;
    }

    float *qkv, *y, *part;
    cudaGetSymbolAddress((void**)&qkv,  g_qkv);
    cudaGetSymbolAddress((void**)&y,    g_y);
    cudaGetSymbolAddress((void**)&part, g_part);

    // QKV projection: split-K=4 -> 384 CTAs (single wave at 3 CTAs/SM)
    gemm_f32<<<dim3(N3_ / 64, 1, 4), 128, GEMM_SMEM>>>(x, w_attn, part, C_, N3_, C_ / 4);
    combine_sk<<<(M_ * N3_ / 4) / 256, 256>>>(part, b_attn, qkv, M_ * N3_, N3_, 4);

    // attention (frozen R10 config)
    attn_partial<<<B_ * H_ * 4, 128, ATTN_SMEM>>>(kc, vc, sp, ic);
    attn_combine<<<B_ * H_ * T_, 128>>>();

    // output projection: split-K=8 -> 256 CTAs (single wave)
    gemm_f32<<<dim3(C_ / 64, 1, 8), 128, GEMM_SMEM>>>(y, w_proj, part, C_, C_, C_ / 8);
    combine_sk<<<(M_ * C_ / 4) / 256, 256>>>(part, b_proj, out, M_ * C_, C_, 8);
}